// round 1
// baseline (speedup 1.0000x reference)
#include <cuda_runtime.h>

// ---------------- fixed problem shapes ----------------
#define NB      64
#define LG      3000
#define LL      2998
#define NNODES  50000
#define NEDGES  800000
#define NE2     (NEDGES + NNODES)
#define KTOT    560          // 40 (global branch) + 520 (local branch)
#define MROWS   (NB * 32)    // 2048

// ---------------- scratch (static device globals; no dynamic alloc) ------
__device__ float d_Atot[MROWS * KTOT];       // [b*32+o][vk]
__device__ float d_Bmat[KTOT * 121];         // [vk][l]
__device__ float d_ysum[MROWS * 121];        // 0.5*(y1+y2) incl bias
__device__ float d_deg[NNODES];
__device__ float d_dinv[NNODES];
__device__ float d_h[NNODES * 33];
__device__ float d_xpacc[NNODES * 33];
__device__ float d_xpbn[NNODES * 33];
__device__ float d_xlr[NNODES * 264];        // [n][j]: j<132 = xl, j>=132 = xr
__device__ float d_ebuf[NE2 * 2];
__device__ float d_emax[NNODES * 2];
__device__ float d_asum[NNODES * 2];
__device__ float d_gatout[NNODES * 132];
__device__ float d_pool[NB * 132];
__device__ float d_cnt[NB];

// ---------------- helpers ----------------
__device__ __forceinline__ void atomicMaxFloat(float* addr, float val) {
    int* ia = (int*)addr;
    int old = __float_as_int(*addr);
    while (__int_as_float(old) < val) {
        int assumed = old;
        old = atomicCAS(ia, assumed, __float_as_int(val));
        if (old == assumed) break;
    }
}

// ---------------- init ----------------
__global__ void k_init() {
    int i = blockIdx.x * blockDim.x + threadIdx.x;
    if (i < MROWS * KTOT)   d_Atot[i] = 0.f;
    if (i < NNODES)         d_deg[i] = 1.0f;          // self-loop weight
    if (i < NNODES * 33)    d_xpacc[i] = 0.f;
    if (i < NNODES * 2)   { d_emax[i] = -1e30f; d_asum[i] = 0.f; }
    if (i < NNODES * 132)   d_gatout[i] = 0.f;
    if (i < NB * 132)       d_pool[i] = 0.f;
    if (i < NB)             d_cnt[i] = 0.f;
}

// ---------------- RNA branch: build A (global, 5 vocab) ----------------
__global__ void k_accA_g(const int* __restrict__ rna, const float* __restrict__ w) {
    __shared__ float acc[5 * 256];
    int b = blockIdx.x, chunk = blockIdx.y, t = threadIdx.x;
    for (int i = t; i < 5 * 256; i += 256) acc[i] = 0.f;
    __syncthreads();
    int c0 = chunk * 500, c1 = c0 + 500;           // 3000 = 6*500
    int o = t >> 3, k = t & 7;
    const float* wp = w + o * (LG * 8) + k;
    for (int c = c0; c < c1; c++) {
        int v = rna[b * LG + c];
        acc[v * 256 + t] += wp[c * 8];
    }
    __syncthreads();
    #pragma unroll
    for (int v = 0; v < 5; v++)
        atomicAdd(&d_Atot[(b * 32 + o) * KTOT + v * 8 + k], acc[v * 256 + t]);
}

// ---------------- RNA branch: build A (local, 65 vocab) ----------------
__global__ void k_accA_l(const int* __restrict__ rna, const float* __restrict__ w) {
    __shared__ float acc[65 * 128];                // 33.3 KB
    int b = blockIdx.x, chunk = blockIdx.y, half = blockIdx.z, t = threadIdx.x;
    for (int i = t; i < 65 * 128; i += 128) acc[i] = 0.f;
    __syncthreads();
    int c0 = chunk * 500;
    int c1 = c0 + 500; if (c1 > LL) c1 = LL;
    int o = half * 16 + (t >> 3), k = t & 7;
    const float* wp = w + o * (LL * 8) + k;
    for (int c = c0; c < c1; c++) {
        int v = rna[b * LL + c];
        acc[v * 128 + t] += wp[c * 8];
    }
    __syncthreads();
    for (int v = 0; v < 65; v++)
        atomicAdd(&d_Atot[(b * 32 + o) * KTOT + 40 + v * 8 + k], acc[v * 128 + t]);
}

// ---------------- build B matrix [560][121] from embeddings ----------------
__global__ void k_bmat(const float* __restrict__ emb1, const float* __restrict__ emb2) {
    int t = blockIdx.x * blockDim.x + threadIdx.x;
    if (t >= KTOT * 121) return;
    int row = t / 121, l = t - row * 121;
    float v;
    if (row < 40)  v = emb1[(row >> 3) * 128 + l + (row & 7)];
    else { int r = row - 40; v = emb2[(r >> 3) * 128 + l + (r & 7)]; }
    d_Bmat[row * 121 + l] = v;
}

// ---------------- GEMM: ysum[2048][121] = Atot[2048][560] x Bmat[560][121] ----
__global__ void k_gemm_ysum(const float* __restrict__ c1b, const float* __restrict__ c2b) {
    __shared__ float Bs[80 * 121];                 // 38.7 KB
    __shared__ float As[8 * 80];
    int t = threadIdx.x;
    int rowbase = blockIdx.x * 8;
    int r = t >> 5, lane = t & 31;
    float a0 = 0.f, a1 = 0.f, a2 = 0.f, a3 = 0.f;
    for (int kc = 0; kc < 7; kc++) {
        for (int i = t; i < 640; i += 256)
            As[i] = d_Atot[(rowbase + i / 80) * KTOT + kc * 80 + (i % 80)];
        for (int i = t; i < 80 * 121; i += 256)
            Bs[i] = d_Bmat[kc * 80 * 121 + i];
        __syncthreads();
        #pragma unroll 8
        for (int kk = 0; kk < 80; kk++) {
            float a = As[r * 80 + kk];
            const float* bp = &Bs[kk * 121];
            a0 += a * bp[lane];
            a1 += a * bp[lane + 32];
            a2 += a * bp[lane + 64];
            if (lane < 25) a3 += a * bp[lane + 96];
        }
        __syncthreads();
    }
    int row = rowbase + r, o = row & 31;
    float bias = c1b[o] + c2b[o];
    float* yp = &d_ysum[row * 121];
    yp[lane]      = 0.5f * (a0 + bias);
    yp[lane + 32] = 0.5f * (a1 + bias);
    yp[lane + 64] = 0.5f * (a2 + bias);
    if (lane < 25) yp[lane + 96] = 0.5f * (a3 + bias);
}

// ---------------- xc_rna = ysum @ fc_xr_w.T + fc_xr_b -> d_out[0:8192] ----
__global__ void k_xc(const float* __restrict__ w, const float* __restrict__ bias,
                     float* __restrict__ out) {
    int b = blockIdx.x >> 7, j = blockIdx.x & 127;
    int t = threadIdx.x;
    const float* y  = &d_ysum[b * 3872];
    const float* wr = &w[j * 3872];
    float s = 0.f;
    for (int i = t; i < 3872; i += 128) s += y[i] * wr[i];
    #pragma unroll
    for (int off = 16; off > 0; off >>= 1) s += __shfl_xor_sync(0xffffffffu, s, off);
    __shared__ float red[4];
    if ((t & 31) == 0) red[t >> 5] = s;
    __syncthreads();
    if (t == 0) out[b * 128 + j] = red[0] + red[1] + red[2] + red[3] + bias[j];
}

// ---------------- GCN: degree / dinv ----------------
__global__ void k_deg(const int* __restrict__ dst, const float* __restrict__ pw, int E) {
    int e = blockIdx.x * blockDim.x + threadIdx.x;
    if (e < E) atomicAdd(&d_deg[dst[e]], pw[e]);
}
__global__ void k_dinv(int N) {
    int n = blockIdx.x * blockDim.x + threadIdx.x;
    if (n < N) d_dinv[n] = rsqrtf(d_deg[n]);
}

// ---------------- h = pro_x @ gcn_w.T ----------------
__global__ void k_h(const float* __restrict__ x, const float* __restrict__ gw, int N) {
    __shared__ float Ws[33 * 33];
    __shared__ float xs[64 * 33];
    int t = threadIdx.x, n0 = blockIdx.x * 64;
    for (int i = t; i < 1089; i += 256) Ws[i] = gw[i];
    for (int i = t; i < 64 * 33; i += 256) {
        int n = n0 + i / 33;
        xs[i] = (n < N) ? x[n0 * 33 + i] : 0.f;
    }
    __syncthreads();
    for (int idx = t; idx < 64 * 33; idx += 256) {
        int nl = idx / 33, j = idx - nl * 33, n = n0 + nl;
        if (n < N) {
            float s = 0.f;
            #pragma unroll
            for (int c = 0; c < 33; c++) s += xs[nl * 33 + c] * Ws[j * 33 + c];
            d_h[n * 33 + j] = s;
        }
    }
}

// ---------------- GCN scatter ----------------
__global__ void k_gcnsc(const int* __restrict__ src, const int* __restrict__ dst,
                        const float* __restrict__ pw, int E) {
    int t = blockIdx.x * blockDim.x + threadIdx.x;
    if (t >= E * 33) return;
    int e = t / 33, j = t - e * 33;
    int s = src[e], d = dst[e];
    float norm = d_dinv[s] * pw[e] * d_dinv[d];
    atomicAdd(&d_xpacc[d * 33 + j], d_h[s * 33 + j] * norm);
}

// ---------------- self-loop + bias + relu + batchnorm ----------------
__global__ void k_bn(const float* __restrict__ gcn_b, const float* __restrict__ bnm,
                     const float* __restrict__ bnv, const float* __restrict__ bnw,
                     const float* __restrict__ bnb, int N) {
    int t = blockIdx.x * blockDim.x + threadIdx.x;
    if (t >= N * 33) return;
    int n = t / 33, j = t - n * 33;
    float di = d_dinv[n];
    float v = d_xpacc[t] + d_h[t] * di * di + gcn_b[j];
    v = fmaxf(v, 0.f);
    float inv = bnw[j] * rsqrtf(bnv[j] + 1e-5f);
    d_xpbn[t] = v * inv + (bnb[j] - bnm[j] * inv);
}

// ---------------- xl / xr = xp_bn @ {wl,wr}.T  (fused, 264-wide) ----------
__global__ void k_xlxr(const float* __restrict__ wl, const float* __restrict__ wr_, int N) {
    __shared__ float Ws[272 * 33];                 // 35.9 KB (rows >=264 zero)
    __shared__ float xs[64 * 33];                  // 8.4 KB
    int t = threadIdx.x, n0 = blockIdx.x * 64;
    for (int i = t; i < 272 * 33; i += 256) {
        int j = i / 33, c = i - j * 33;
        float v = 0.f;
        if (j < 132)      v = wl[j * 33 + c];
        else if (j < 264) v = wr_[(j - 132) * 33 + c];
        Ws[i] = v;
    }
    for (int i = t; i < 64 * 33; i += 256) {
        int n = n0 + i / 33;
        xs[i] = (n < N) ? d_xpbn[n0 * 33 + i] : 0.f;
    }
    __syncthreads();
    int tx = t & 15, ty = t >> 4;                  // 16 j-groups x 16 node-groups
    float acc[4][17];
    #pragma unroll
    for (int a = 0; a < 4; a++)
        #pragma unroll
        for (int u = 0; u < 17; u++) acc[a][u] = 0.f;
    for (int c = 0; c < 33; c++) {
        float xv0 = xs[(ty * 4 + 0) * 33 + c];
        float xv1 = xs[(ty * 4 + 1) * 33 + c];
        float xv2 = xs[(ty * 4 + 2) * 33 + c];
        float xv3 = xs[(ty * 4 + 3) * 33 + c];
        #pragma unroll
        for (int u = 0; u < 17; u++) {
            float wv = Ws[(tx * 17 + u) * 33 + c];
            acc[0][u] += xv0 * wv; acc[1][u] += xv1 * wv;
            acc[2][u] += xv2 * wv; acc[3][u] += xv3 * wv;
        }
    }
    #pragma unroll
    for (int a = 0; a < 4; a++) {
        int n = n0 + ty * 4 + a;
        if (n < N) {
            #pragma unroll
            for (int u = 0; u < 17; u++) {
                int j = tx * 17 + u;
                if (j < 264) d_xlr[n * 264 + j] = acc[a][u];
            }
        }
    }
}

// ---------------- GAT pass 1: logits + segment max (warp per edge) -------
__global__ void k_att1(const int* __restrict__ src, const int* __restrict__ dst,
                       const float* __restrict__ att, int E, int e2v) {
    int e = blockIdx.x * 8 + (threadIdx.x >> 5);
    if (e >= e2v) return;
    int lane = threadIdx.x & 31;
    int s, d;
    if (e < E) { s = src[e]; d = dst[e]; } else { s = d = e - E; }
    const float* xls = &d_xlr[s * 264];
    const float* xrd = &d_xlr[d * 264 + 132];
    float e0 = 0.f, e1 = 0.f;
    for (int c = lane; c < 66; c += 32) {
        float v0 = xls[c] + xrd[c];           v0 = v0 > 0.f ? v0 : 0.2f * v0;
        float v1 = xls[66 + c] + xrd[66 + c]; v1 = v1 > 0.f ? v1 : 0.2f * v1;
        e0 += v0 * att[c];
        e1 += v1 * att[66 + c];
    }
    #pragma unroll
    for (int off = 16; off > 0; off >>= 1) {
        e0 += __shfl_xor_sync(0xffffffffu, e0, off);
        e1 += __shfl_xor_sync(0xffffffffu, e1, off);
    }
    if (lane == 0) {
        d_ebuf[e * 2]     = e0;
        d_ebuf[e * 2 + 1] = e1;
        atomicMaxFloat(&d_emax[d * 2],     e0);
        atomicMaxFloat(&d_emax[d * 2 + 1], e1);
    }
}

// ---------------- GAT pass 2: exp + segment sum ----------------
__global__ void k_att2(const int* __restrict__ dst, int E, int e2v) {
    int t = blockIdx.x * blockDim.x + threadIdx.x;
    if (t >= e2v * 2) return;
    int e = t >> 1, h = t & 1;
    int d = (e < E) ? dst[e] : e - E;
    float a = expf(d_ebuf[t] - d_emax[d * 2 + h]);
    d_ebuf[t] = a;
    atomicAdd(&d_asum[d * 2 + h], a);
}

// ---------------- GAT pass 3: normalize + weighted scatter ---------------
__global__ void k_att3(const int* __restrict__ src, const int* __restrict__ dst,
                       int E, int e2v) {
    int t = blockIdx.x * blockDim.x + threadIdx.x;
    long long total = (long long)e2v * 132;
    if (t >= total) return;
    int e = t / 132, j = t - e * 132;
    int h = (j >= 66) ? 1 : 0;
    int s, d;
    if (e < E) { s = src[e]; d = dst[e]; } else { s = d = e - E; }
    float alpha = d_ebuf[e * 2 + h] / d_asum[d * 2 + h];
    atomicAdd(&d_gatout[d * 132 + j], d_xlr[s * 264 + j] * alpha);
}

// ---------------- bias+relu+pool ----------------
__global__ void k_pool(const float* __restrict__ gat_b, const int* __restrict__ batch, int N) {
    int t = blockIdx.x * blockDim.x + threadIdx.x;
    if (t >= N * 132) return;
    int n = t / 132, j = t - n * 132;
    float v = fmaxf(d_gatout[t] + gat_b[j], 0.f);
    atomicAdd(&d_pool[batch[n] * 132 + j], v);
}
__global__ void k_cnt(const int* __restrict__ batch, int N) {
    int n = blockIdx.x * blockDim.x + threadIdx.x;
    if (n < N) atomicAdd(&d_cnt[batch[n]], 1.0f);
}

// ---------------- MLP head -> d_out[8192:16384] ----------------
__global__ void k_mlp(const float* __restrict__ w1, const float* __restrict__ b1,
                      const float* __restrict__ w2, const float* __restrict__ b2,
                      float* __restrict__ out) {
    __shared__ float xp[132];
    __shared__ float z[1024];
    int g = blockIdx.x, t = threadIdx.x;
    if (t < 132) xp[t] = d_pool[g * 132 + t] / fmaxf(d_cnt[g], 1.0f);
    __syncthreads();
    for (int u = t; u < 1024; u += 256) {
        float a = b1[u];
        const float* wr = &w1[u * 132];
        #pragma unroll 4
        for (int i = 0; i < 132; i++) a += xp[i] * wr[i];
        z[u] = fmaxf(a, 0.f);
    }
    __syncthreads();
    if (t < 128) {
        float a = b2[t];
        const float* wr = &w2[t * 1024];
        #pragma unroll 4
        for (int i = 0; i < 1024; i++) a += z[i] * wr[i];
        out[8192 + g * 128 + t] = a;
    }
}

// ---------------- host launcher ----------------
extern "C" void kernel_launch(void* const* d_in, const int* in_sizes, int n_in,
                              void* d_out, int out_size) {
    const int*   global_rna = (const int*)d_in[0];
    const int*   local_rna  = (const int*)d_in[1];
    const float* pro_x      = (const float*)d_in[2];
    const int*   edge_index = (const int*)d_in[3];
    const float* pro_weight = (const float*)d_in[4];
    const int*   pro_batch  = (const int*)d_in[5];
    const float* emb1       = (const float*)d_in[6];
    const float* emb2       = (const float*)d_in[7];
    const float* conv1_w    = (const float*)d_in[8];
    const float* conv1_b    = (const float*)d_in[9];
    const float* conv2_w    = (const float*)d_in[10];
    const float* conv2_b    = (const float*)d_in[11];
    const float* fc_xr_w    = (const float*)d_in[12];
    const float* fc_xr_b    = (const float*)d_in[13];
    const float* gcn_w      = (const float*)d_in[14];
    const float* gcn_b      = (const float*)d_in[15];
    const float* bn_mean    = (const float*)d_in[16];
    const float* bn_var     = (const float*)d_in[17];
    const float* bn_weight  = (const float*)d_in[18];
    const float* bn_bias    = (const float*)d_in[19];
    const float* gat_wl     = (const float*)d_in[20];
    const float* gat_wr     = (const float*)d_in[21];
    const float* gat_att    = (const float*)d_in[22];
    const float* gat_b      = (const float*)d_in[23];
    const float* fc1_w      = (const float*)d_in[24];
    const float* fc1_b      = (const float*)d_in[25];
    const float* fc2_w      = (const float*)d_in[26];
    const float* fc2_b      = (const float*)d_in[27];
    float* out = (float*)d_out;

    int E  = in_sizes[3] / 2;
    int N  = in_sizes[2] / 33;
    int e2 = E + N;
    const int* src = edge_index;
    const int* dst = edge_index + E;

    k_init<<<(NNODES * 132 + 255) / 256, 256>>>();

    // RNA branch
    k_accA_g<<<dim3(NB, 6), 256>>>(global_rna, conv1_w);
    k_accA_l<<<dim3(NB, 6, 2), 128>>>(local_rna, conv2_w);
    k_bmat<<<(KTOT * 121 + 255) / 256, 256>>>(emb1, emb2);
    k_gemm_ysum<<<MROWS / 8, 256>>>(conv1_b, conv2_b);
    k_xc<<<NB * 128, 128>>>(fc_xr_w, fc_xr_b, out);

    // GCN
    k_deg<<<(E + 255) / 256, 256>>>(dst, pro_weight, E);
    k_dinv<<<(N + 255) / 256, 256>>>(N);
    k_h<<<(N + 63) / 64, 256>>>(pro_x, gcn_w, N);
    k_gcnsc<<<(E * 33 + 255) / 256, 256>>>(src, dst, pro_weight, E);
    k_bn<<<(N * 33 + 255) / 256, 256>>>(gcn_b, bn_mean, bn_var, bn_weight, bn_bias, N);

    // GATv2
    k_xlxr<<<(N + 63) / 64, 256>>>(gat_wl, gat_wr, N);
    k_att1<<<(e2 + 7) / 8, 256>>>(src, dst, gat_att, E, e2);
    k_att2<<<(e2 * 2 + 255) / 256, 256>>>(dst, E, e2);
    {
        long long tot = (long long)e2 * 132;
        int blocks = (int)((tot + 255) / 256);
        k_att3<<<blocks, 256>>>(src, dst, E, e2);
    }

    // pooling + MLP
    k_pool<<<(N * 132 + 255) / 256, 256>>>(gat_b, pro_batch, N);
    k_cnt<<<(N + 255) / 256, 256>>>(pro_batch, N);
    k_mlp<<<NB, 256>>>(fc1_w, fc1_b, fc2_w, fc2_b, out);
}

// round 2
// speedup vs baseline: 1.7009x; 1.7009x over previous
#include <cuda_runtime.h>

// ---------------- fixed problem shapes ----------------
#define NB      64
#define LG      3000
#define LL      2998
#define NNODES  50000
#define NEDGES  800000
#define NE2     (NEDGES + NNODES)
#define KTOT    560          // 40 (global branch) + 520 (local branch)
#define MROWS   (NB * 32)    // 2048

// ---------------- scratch (static device globals) ------
__device__ float d_Atot[MROWS * KTOT];
__device__ float d_Bmat[KTOT * 121];
__device__ float d_ysum[MROWS * 121];
__device__ float d_deg[NNODES];
__device__ float d_dinv[NNODES];
__device__ float d_h[NNODES * 33];
__device__ float d_xpbn[NNODES * 33];
__device__ float d_xlr[NNODES * 264];        // [n][j]: j<132 = xl, j>=132 = xr
__device__ float d_pool[NB * 132];
__device__ int   d_cnti[NB];
// CSR (grouped by dst)
__device__ int   d_rowcnt[NNODES];
__device__ int   d_rowoff[NNODES + 1];
__device__ int   d_cursor[NNODES];
__device__ int   d_csrc[NE2];
__device__ float d_cnorm[NE2];

// ---------------- init ----------------
__global__ void k_init() {
    int i = blockIdx.x * blockDim.x + threadIdx.x;
    if (i < MROWS * KTOT)   d_Atot[i] = 0.f;
    if (i < NNODES)       { d_deg[i] = 1.0f; d_rowcnt[i] = 1; }  // self-loop
    if (i < NB * 132)       d_pool[i] = 0.f;
    if (i < NB)             d_cnti[i] = 0;
}

// ---------------- degree + indegree count ----------------
__global__ void k_degcnt(const int* __restrict__ dst, const float* __restrict__ pw, int E) {
    int e = blockIdx.x * blockDim.x + threadIdx.x;
    if (e < E) {
        int d = dst[e];
        atomicAdd(&d_deg[d], pw[e]);
        atomicAdd(&d_rowcnt[d], 1);
    }
}
__global__ void k_dinv(int N) {
    int n = blockIdx.x * blockDim.x + threadIdx.x;
    if (n < N) d_dinv[n] = rsqrtf(d_deg[n]);
}

// ---------------- single-block exclusive scan of rowcnt -> rowoff ----------
__global__ void k_scan(int N) {
    __shared__ int sh[1024];
    __shared__ int carry_s;
    int tid = threadIdx.x;
    if (tid == 0) carry_s = 0;
    __syncthreads();
    for (int base = 0; base <= N; base += 1024) {
        int i = base + tid;
        int v = (i < N) ? d_rowcnt[i] : 0;
        sh[tid] = v;
        __syncthreads();
        #pragma unroll
        for (int off = 1; off < 1024; off <<= 1) {
            int t = (tid >= off) ? sh[tid - off] : 0;
            __syncthreads();
            sh[tid] += t;
            __syncthreads();
        }
        int c = carry_s;
        int excl = c + sh[tid] - v;
        if (i <= N) {
            d_rowoff[i] = excl;
            if (i < N) d_cursor[i] = excl;
        }
        __syncthreads();
        if (tid == 0) carry_s = c + sh[1023];
        __syncthreads();
    }
}

// ---------------- CSR fill (with precomputed GCN norm) ----------------
__global__ void k_csr_fill(const int* __restrict__ src, const int* __restrict__ dst,
                           const float* __restrict__ pw, int E, int e2) {
    int e = blockIdx.x * blockDim.x + threadIdx.x;
    if (e >= e2) return;
    int s, d; float w;
    if (e < E) { s = src[e]; d = dst[e]; w = pw[e]; }
    else       { s = d = e - E; w = 1.f; }
    int pos = atomicAdd(&d_cursor[d], 1);
    d_csrc[pos] = s;
    d_cnorm[pos] = d_dinv[s] * w * d_dinv[d];
}

// ---------------- RNA branch: build A (global, 5 vocab) ----------------
__global__ void k_accA_g(const int* __restrict__ rna, const float* __restrict__ w) {
    __shared__ float acc[5 * 256];
    int b = blockIdx.x, chunk = blockIdx.y, t = threadIdx.x;
    for (int i = t; i < 5 * 256; i += 256) acc[i] = 0.f;
    __syncthreads();
    int c0 = chunk * 500, c1 = c0 + 500;
    int o = t >> 3, k = t & 7;
    const float* wp = w + o * (LG * 8) + k;
    for (int c = c0; c < c1; c++) {
        int v = rna[b * LG + c];
        acc[v * 256 + t] += wp[c * 8];
    }
    __syncthreads();
    #pragma unroll
    for (int v = 0; v < 5; v++)
        atomicAdd(&d_Atot[(b * 32 + o) * KTOT + v * 8 + k], acc[v * 256 + t]);
}

// ---------------- RNA branch: build A (local, 65 vocab) ----------------
__global__ void k_accA_l(const int* __restrict__ rna, const float* __restrict__ w) {
    __shared__ float acc[65 * 128];
    int b = blockIdx.x, chunk = blockIdx.y, half = blockIdx.z, t = threadIdx.x;
    for (int i = t; i < 65 * 128; i += 128) acc[i] = 0.f;
    __syncthreads();
    int c0 = chunk * 500;
    int c1 = c0 + 500; if (c1 > LL) c1 = LL;
    int o = half * 16 + (t >> 3), k = t & 7;
    const float* wp = w + o * (LL * 8) + k;
    for (int c = c0; c < c1; c++) {
        int v = rna[b * LL + c];
        acc[v * 128 + t] += wp[c * 8];
    }
    __syncthreads();
    for (int v = 0; v < 65; v++)
        atomicAdd(&d_Atot[(b * 32 + o) * KTOT + 40 + v * 8 + k], acc[v * 128 + t]);
}

// ---------------- build B matrix [560][121] ----------------
__global__ void k_bmat(const float* __restrict__ emb1, const float* __restrict__ emb2) {
    int t = blockIdx.x * blockDim.x + threadIdx.x;
    if (t >= KTOT * 121) return;
    int row = t / 121, l = t - row * 121;
    float v;
    if (row < 40)  v = emb1[(row >> 3) * 128 + l + (row & 7)];
    else { int r = row - 40; v = emb2[(r >> 3) * 128 + l + (r & 7)]; }
    d_Bmat[row * 121 + l] = v;
}

// ---------------- GEMM: ysum[2048][121] = Atot x Bmat ----
__global__ void k_gemm_ysum(const float* __restrict__ c1b, const float* __restrict__ c2b) {
    __shared__ float Bs[80 * 121];
    __shared__ float As[8 * 80];
    int t = threadIdx.x;
    int rowbase = blockIdx.x * 8;
    int r = t >> 5, lane = t & 31;
    float a0 = 0.f, a1 = 0.f, a2 = 0.f, a3 = 0.f;
    for (int kc = 0; kc < 7; kc++) {
        for (int i = t; i < 640; i += 256)
            As[i] = d_Atot[(rowbase + i / 80) * KTOT + kc * 80 + (i % 80)];
        for (int i = t; i < 80 * 121; i += 256)
            Bs[i] = d_Bmat[kc * 80 * 121 + i];
        __syncthreads();
        #pragma unroll 8
        for (int kk = 0; kk < 80; kk++) {
            float a = As[r * 80 + kk];
            const float* bp = &Bs[kk * 121];
            a0 += a * bp[lane];
            a1 += a * bp[lane + 32];
            a2 += a * bp[lane + 64];
            if (lane < 25) a3 += a * bp[lane + 96];
        }
        __syncthreads();
    }
    int row = rowbase + r, o = row & 31;
    float bias = c1b[o] + c2b[o];
    float* yp = &d_ysum[row * 121];
    yp[lane]      = 0.5f * (a0 + bias);
    yp[lane + 32] = 0.5f * (a1 + bias);
    yp[lane + 64] = 0.5f * (a2 + bias);
    if (lane < 25) yp[lane + 96] = 0.5f * (a3 + bias);
}

// ---------------- xc_rna = ysum @ fc_xr_w.T + b -> out[0:8192] ----
// grid 128 = 16 j-tiles x 8 b-tiles; block 256 = 8 warps (one per j)
__global__ void k_xc(const float* __restrict__ w, const float* __restrict__ bias,
                     float* __restrict__ out) {
    __shared__ float ys[3872];
    int jt = blockIdx.x & 15, bt = blockIdx.x >> 4;
    int t = threadIdx.x, warp = t >> 5, lane = t & 31;
    int j = jt * 8 + warp;
    const float* wr = &w[j * 3872];
    for (int bi = 0; bi < 8; bi++) {
        int b = bt * 8 + bi;
        __syncthreads();
        for (int i = t; i < 3872; i += 256) ys[i] = d_ysum[b * 3872 + i];
        __syncthreads();
        float s = 0.f;
        for (int i = lane; i < 3872; i += 32) s += ys[i] * wr[i];
        #pragma unroll
        for (int off = 16; off > 0; off >>= 1) s += __shfl_xor_sync(0xffffffffu, s, off);
        if (lane == 0) out[b * 128 + j] = s + bias[j];
    }
}

// ---------------- h = pro_x @ gcn_w.T ----------------
__global__ void k_h(const float* __restrict__ x, const float* __restrict__ gw, int N) {
    __shared__ float Ws[33 * 33];
    __shared__ float xs[64 * 33];
    int t = threadIdx.x, n0 = blockIdx.x * 64;
    for (int i = t; i < 1089; i += 256) Ws[i] = gw[i];
    for (int i = t; i < 64 * 33; i += 256) {
        int n = n0 + i / 33;
        xs[i] = (n < N) ? x[n0 * 33 + i] : 0.f;
    }
    __syncthreads();
    for (int idx = t; idx < 64 * 33; idx += 256) {
        int nl = idx / 33, j = idx - nl * 33, n = n0 + nl;
        if (n < N) {
            float s = 0.f;
            #pragma unroll
            for (int c = 0; c < 33; c++) s += xs[nl * 33 + c] * Ws[j * 33 + c];
            d_h[n * 33 + j] = s;
        }
    }
}

// ---------------- GCN gather (warp per node) + bias/relu/BN fused -------
__global__ void k_gcn_csr(const float* __restrict__ gcn_b, const float* __restrict__ bnm,
                          const float* __restrict__ bnv, const float* __restrict__ bnw,
                          const float* __restrict__ bnb, int N) {
    int wid = (blockIdx.x * blockDim.x + threadIdx.x) >> 5;
    int lane = threadIdx.x & 31;
    if (wid >= N) return;
    int st = d_rowoff[wid], en = d_rowoff[wid + 1];
    float acc0 = 0.f, acc1 = 0.f;
    for (int i = st; i < en; i++) {
        int s = d_csrc[i];
        float nm = d_cnorm[i];
        const float* hp = &d_h[s * 33];
        acc0 += nm * hp[lane];
        if (lane == 0) acc1 += nm * hp[32];
    }
    float v = fmaxf(acc0 + gcn_b[lane], 0.f);
    float inv = bnw[lane] * rsqrtf(bnv[lane] + 1e-5f);
    d_xpbn[wid * 33 + lane] = v * inv + (bnb[lane] - bnm[lane] * inv);
    if (lane == 0) {
        float v2 = fmaxf(acc1 + gcn_b[32], 0.f);
        float inv2 = bnw[32] * rsqrtf(bnv[32] + 1e-5f);
        d_xpbn[wid * 33 + 32] = v2 * inv2 + (bnb[32] - bnm[32] * inv2);
    }
}

// ---------------- xl / xr = xp_bn @ {wl,wr}.T (fused, 264-wide) ----------
__global__ void k_xlxr(const float* __restrict__ wl, const float* __restrict__ wr_, int N) {
    __shared__ float Ws[272 * 33];
    __shared__ float xs[64 * 33];
    int t = threadIdx.x, n0 = blockIdx.x * 64;
    for (int i = t; i < 272 * 33; i += 256) {
        int j = i / 33, c = i - j * 33;
        float v = 0.f;
        if (j < 132)      v = wl[j * 33 + c];
        else if (j < 264) v = wr_[(j - 132) * 33 + c];
        Ws[i] = v;
    }
    for (int i = t; i < 64 * 33; i += 256) {
        int n = n0 + i / 33;
        xs[i] = (n < N) ? d_xpbn[n0 * 33 + i] : 0.f;
    }
    __syncthreads();
    int tx = t & 15, ty = t >> 4;
    float acc[4][17];
    #pragma unroll
    for (int a = 0; a < 4; a++)
        #pragma unroll
        for (int u = 0; u < 17; u++) acc[a][u] = 0.f;
    for (int c = 0; c < 33; c++) {
        float xv0 = xs[(ty * 4 + 0) * 33 + c];
        float xv1 = xs[(ty * 4 + 1) * 33 + c];
        float xv2 = xs[(ty * 4 + 2) * 33 + c];
        float xv3 = xs[(ty * 4 + 3) * 33 + c];
        #pragma unroll
        for (int u = 0; u < 17; u++) {
            float wv = Ws[(tx * 17 + u) * 33 + c];
            acc[0][u] += xv0 * wv; acc[1][u] += xv1 * wv;
            acc[2][u] += xv2 * wv; acc[3][u] += xv3 * wv;
        }
    }
    #pragma unroll
    for (int a = 0; a < 4; a++) {
        int n = n0 + ty * 4 + a;
        if (n < N) {
            #pragma unroll
            for (int u = 0; u < 17; u++) {
                int j = tx * 17 + u;
                if (j < 264) d_xlr[n * 264 + j] = acc[a][u];
            }
        }
    }
}

// ---------------- GAT: one pass, warp per node, online softmax ----------
// fused bias + relu + global-mean-pool accumulation
__global__ void k_gat_csr(const float* __restrict__ att, const float* __restrict__ gat_b,
                          const int* __restrict__ batch, int N) {
    int wid = (blockIdx.x * blockDim.x + threadIdx.x) >> 5;
    int lane = threadIdx.x & 31;
    if (wid >= N) return;
    int n = wid;
    int f0 = lane, f1 = lane + 32, f2 = lane + 64, f3 = lane + 96, f4 = lane + 128;
    bool has4 = lane < 4;
    bool h0f2 = lane < 2;                // feature f2 < 66 only for lanes 0,1
    const float* xrd = &d_xlr[n * 264 + 132];
    float xr0 = xrd[f0], xr1 = xrd[f1], xr2 = xrd[f2], xr3 = xrd[f3];
    float xr4 = has4 ? xrd[f4] : 0.f;
    float a0 = att[f0], a1 = att[f1], a2 = att[f2], a3 = att[f3];
    float a4 = has4 ? att[f4] : 0.f;
    float m0 = -1e30f, m1 = -1e30f, l0 = 0.f, l1 = 0.f;
    float acc0 = 0.f, acc1 = 0.f, acc2 = 0.f, acc3 = 0.f, acc4 = 0.f;
    int st = d_rowoff[n], en = d_rowoff[n + 1];
    for (int i = st; i < en; i++) {
        int s = d_csrc[i];
        const float* xls = &d_xlr[s * 264];
        float x0 = xls[f0], x1 = xls[f1], x2 = xls[f2], x3 = xls[f3];
        float x4 = has4 ? xls[f4] : 0.f;
        float t, p0, p1;
        t = x0 + xr0; t = t > 0.f ? t : 0.2f * t; p0 = t * a0;
        t = x1 + xr1; t = t > 0.f ? t : 0.2f * t; p0 += t * a1;
        t = x2 + xr2; t = t > 0.f ? t : 0.2f * t;
        float c2 = t * a2;
        p1 = h0f2 ? 0.f : c2;
        if (h0f2) p0 += c2;
        t = x3 + xr3; t = t > 0.f ? t : 0.2f * t; p1 += t * a3;
        t = x4 + xr4; t = t > 0.f ? t : 0.2f * t; p1 += t * a4;  // a4=0 for lane>=4
        #pragma unroll
        for (int off = 16; off > 0; off >>= 1) {
            p0 += __shfl_xor_sync(0xffffffffu, p0, off);
            p1 += __shfl_xor_sync(0xffffffffu, p1, off);
        }
        float mn0 = fmaxf(m0, p0), mn1 = fmaxf(m1, p1);
        float sc0 = __expf(m0 - mn0), sc1 = __expf(m1 - mn1);
        float w0  = __expf(p0 - mn0), w1  = __expf(p1 - mn1);
        l0 = l0 * sc0 + w0; l1 = l1 * sc1 + w1;
        m0 = mn0; m1 = mn1;
        float scf2 = h0f2 ? sc0 : sc1, wf2 = h0f2 ? w0 : w1;
        acc0 = acc0 * sc0  + w0  * x0;
        acc1 = acc1 * sc0  + w0  * x1;
        acc2 = acc2 * scf2 + wf2 * x2;
        acc3 = acc3 * sc1  + w1  * x3;
        acc4 = acc4 * sc1  + w1  * x4;
    }
    int g = batch[n];
    float inv0 = 1.f / l0, inv1 = 1.f / l1;
    float o;
    o = fmaxf(acc0 * inv0 + gat_b[f0], 0.f); atomicAdd(&d_pool[g * 132 + f0], o);
    o = fmaxf(acc1 * inv0 + gat_b[f1], 0.f); atomicAdd(&d_pool[g * 132 + f1], o);
    o = fmaxf(acc2 * (h0f2 ? inv0 : inv1) + gat_b[f2], 0.f); atomicAdd(&d_pool[g * 132 + f2], o);
    o = fmaxf(acc3 * inv1 + gat_b[f3], 0.f); atomicAdd(&d_pool[g * 132 + f3], o);
    if (has4) { o = fmaxf(acc4 * inv1 + gat_b[f4], 0.f); atomicAdd(&d_pool[g * 132 + f4], o); }
    if (lane == 0) atomicAdd(&d_cnti[g], 1);
}

// ---------------- MLP head -> out[8192:16384] ----------------
__global__ void k_mlp(const float* __restrict__ w1, const float* __restrict__ b1,
                      const float* __restrict__ w2, const float* __restrict__ b2,
                      float* __restrict__ out) {
    __shared__ float xp[132];
    __shared__ float z[1024];
    int g = blockIdx.x, t = threadIdx.x;
    if (t < 132) xp[t] = d_pool[g * 132 + t] / fmaxf((float)d_cnti[g], 1.0f);
    __syncthreads();
    for (int u = t; u < 1024; u += 256) {
        float a = b1[u];
        const float* wr = &w1[u * 132];
        #pragma unroll 4
        for (int i = 0; i < 132; i++) a += xp[i] * wr[i];
        z[u] = fmaxf(a, 0.f);
    }
    __syncthreads();
    if (t < 128) {
        float a = b2[t];
        const float* wr = &w2[t * 1024];
        #pragma unroll 4
        for (int i = 0; i < 1024; i++) a += z[i] * wr[i];
        out[8192 + g * 128 + t] = a;
    }
}

// ---------------- host launcher ----------------
extern "C" void kernel_launch(void* const* d_in, const int* in_sizes, int n_in,
                              void* d_out, int out_size) {
    const int*   global_rna = (const int*)d_in[0];
    const int*   local_rna  = (const int*)d_in[1];
    const float* pro_x      = (const float*)d_in[2];
    const int*   edge_index = (const int*)d_in[3];
    const float* pro_weight = (const float*)d_in[4];
    const int*   pro_batch  = (const int*)d_in[5];
    const float* emb1       = (const float*)d_in[6];
    const float* emb2       = (const float*)d_in[7];
    const float* conv1_w    = (const float*)d_in[8];
    const float* conv1_b    = (const float*)d_in[9];
    const float* conv2_w    = (const float*)d_in[10];
    const float* conv2_b    = (const float*)d_in[11];
    const float* fc_xr_w    = (const float*)d_in[12];
    const float* fc_xr_b    = (const float*)d_in[13];
    const float* gcn_w      = (const float*)d_in[14];
    const float* gcn_b      = (const float*)d_in[15];
    const float* bn_mean    = (const float*)d_in[16];
    const float* bn_var     = (const float*)d_in[17];
    const float* bn_weight  = (const float*)d_in[18];
    const float* bn_bias    = (const float*)d_in[19];
    const float* gat_wl     = (const float*)d_in[20];
    const float* gat_wr     = (const float*)d_in[21];
    const float* gat_att    = (const float*)d_in[22];
    const float* gat_b      = (const float*)d_in[23];
    const float* fc1_w      = (const float*)d_in[24];
    const float* fc1_b      = (const float*)d_in[25];
    const float* fc2_w      = (const float*)d_in[26];
    const float* fc2_b      = (const float*)d_in[27];
    float* out = (float*)d_out;

    int E  = in_sizes[3] / 2;
    int N  = in_sizes[2] / 33;
    int e2 = E + N;
    const int* src = edge_index;
    const int* dst = edge_index + E;

    k_init<<<(MROWS * KTOT + 255) / 256, 256>>>();

    // graph preprocessing: degrees + CSR by dst
    k_degcnt<<<(E + 255) / 256, 256>>>(dst, pro_weight, E);
    k_dinv<<<(N + 255) / 256, 256>>>(N);
    k_scan<<<1, 1024>>>(N);
    k_csr_fill<<<(e2 + 255) / 256, 256>>>(src, dst, pro_weight, E, e2);

    // RNA branch
    k_accA_g<<<dim3(NB, 6), 256>>>(global_rna, conv1_w);
    k_accA_l<<<dim3(NB, 6, 2), 128>>>(local_rna, conv2_w);
    k_bmat<<<(KTOT * 121 + 255) / 256, 256>>>(emb1, emb2);
    k_gemm_ysum<<<MROWS / 8, 256>>>(conv1_b, conv2_b);
    k_xc<<<128, 256>>>(fc_xr_w, fc_xr_b, out);

    // GCN
    k_h<<<(N + 63) / 64, 256>>>(pro_x, gcn_w, N);
    k_gcn_csr<<<(N * 32 + 255) / 256, 256>>>(gcn_b, bn_mean, bn_var, bn_weight, bn_bias, N);

    // GATv2 (single fused pass) + pooling
    k_xlxr<<<(N + 63) / 64, 256>>>(gat_wl, gat_wr, N);
    k_gat_csr<<<(N * 32 + 255) / 256, 256>>>(gat_att, gat_b, pro_batch, N);

    // MLP head
    k_mlp<<<NB, 256>>>(fc1_w, fc1_b, fc2_w, fc2_b, out);
}